// round 1
// baseline (speedup 1.0000x reference)
#include <cuda_runtime.h>

#define DTV      0.02f
#define SQRT_DT  0.141421356237309515f
#define SIGMA    0.5f
#define NSTEP    50
#define BATCH    4096
#define PPC      32            // paths per CTA
#define NCTA     (BATCH / PPC) // 128
#define NTHR     128

// ---- shared-memory layout (float offsets) ----
// per-net block:
#define W_IN   0       // [2][64] = 128
#define B_IN   128     // 64
#define W_H    192     // [3][64][64] = 12288
#define B_H    12480   // [3][64] = 192
#define W_OUT  12672   // 64
#define B_OUT  12736   // 1 (+3 pad)
#define NET_SZ 12740
// activations (hidden-major, path-minor [64][32]):
#define OFF_X    (2 * NET_SZ)        // 25480
#define OFF_DX   (OFF_X  + 2048)
#define OFF_XN   (OFF_DX + 2048)
#define OFF_DXN  (OFF_XN + 2048)
#define OFF_YS   (OFF_DXN + 2048)    // 32 path states y
#define SMEM_FLOATS (OFF_YS + 32)
#define SMEM_BYTES  (SMEM_FLOATS * 4)

__device__ float g_acc;

__global__ void k_init() { g_acc = 0.0f; }

__global__ void k_fin(float* out) { out[0] = g_acc * (1.0f / (float)BATCH); }

__device__ __forceinline__ void cpf(float* d, const float* s, int n, int tid) {
    for (int i = tid; i < n; i += NTHR) d[i] = s[i];
}

// One hidden layer: Xn[j][p] = sin( sum_i X[i][p] * W[i][j] + b[j] )
// and (if TANG) dXn[j][p] = cos(a) * sum_i dX[i][p] * W[i][j]
template <bool TANG>
__device__ __forceinline__ void hidden_layer(
    const float* __restrict__ W, const float* __restrict__ b,
    const float* __restrict__ X, const float* __restrict__ dXb,
    float* __restrict__ Xn, float* __restrict__ dXn,
    int jg, int pg)
{
    const float4* W4  = (const float4*)W;
    const float4* X4  = (const float4*)X;
    const float4* dX4 = (const float4*)dXb;

    float ah[4][4];
    float ad[4][4];
#pragma unroll
    for (int a = 0; a < 4; a++)
#pragma unroll
        for (int c = 0; c < 4; c++) { ah[a][c] = 0.0f; ad[a][c] = 0.0f; }

#pragma unroll 8
    for (int i = 0; i < 64; i++) {
        float4 w = W4[i * 16 + jg];
        float4 x = X4[i * 8 + pg];
        float wv[4] = {w.x, w.y, w.z, w.w};
        float xv[4] = {x.x, x.y, x.z, x.w};
#pragma unroll
        for (int jj = 0; jj < 4; jj++)
#pragma unroll
            for (int pp = 0; pp < 4; pp++)
                ah[jj][pp] = fmaf(wv[jj], xv[pp], ah[jj][pp]);
        if (TANG) {
            float4 dx = dX4[i * 8 + pg];
            float dv[4] = {dx.x, dx.y, dx.z, dx.w};
#pragma unroll
            for (int jj = 0; jj < 4; jj++)
#pragma unroll
                for (int pp = 0; pp < 4; pp++)
                    ad[jj][pp] = fmaf(wv[jj], dv[pp], ad[jj][pp]);
        }
    }

    int j0 = jg * 4, p0 = pg * 4;
#pragma unroll
    for (int jj = 0; jj < 4; jj++) {
        float bj = b[j0 + jj];
        float s[4], c[4];
#pragma unroll
        for (int pp = 0; pp < 4; pp++) {
            float a = ah[jj][pp] + bj;
            __sincosf(a, &s[pp], &c[pp]);
        }
        *(float4*)&Xn[(j0 + jj) * PPC + p0] = make_float4(s[0], s[1], s[2], s[3]);
        if (TANG) {
            *(float4*)&dXn[(j0 + jj) * PPC + p0] =
                make_float4(c[0] * ad[jj][0], c[1] * ad[jj][1],
                            c[2] * ad[jj][2], c[3] * ad[jj][3]);
        }
    }
}

// Full net evaluation at time tval on state ys[] (in smem).
// If TANG: also propagates the tangent d/dy and returns doutv.
// outv/doutv valid only for tid < 32 (thread p owns path p).
template <bool TANG>
__device__ __forceinline__ void eval_net(
    const float* __restrict__ net, float* __restrict__ sm, float tval,
    int jg, int pg, int tid, float& outv, float& doutv)
{
    float* X   = sm + OFF_X;
    float* dXb = sm + OFF_DX;
    float* Xn  = sm + OFF_XN;
    float* dXn = sm + OFF_DXN;
    const float* ys = sm + OFF_YS;

    int j0 = jg * 4, p0 = pg * 4;
    // ---- input layer: concat([t, y]) @ Win + bin, Sine ----
#pragma unroll
    for (int jj = 0; jj < 4; jj++) {
        int j = j0 + jj;
        float wt = net[W_IN + j];
        float wy = net[W_IN + 64 + j];
        float bj = net[B_IN + j];
        float s[4], c[4];
#pragma unroll
        for (int pp = 0; pp < 4; pp++) {
            float a = fmaf(tval, wt, fmaf(ys[p0 + pp], wy, bj));
            __sincosf(a, &s[pp], &c[pp]);
        }
        *(float4*)&X[j * PPC + p0] = make_float4(s[0], s[1], s[2], s[3]);
        if (TANG) {
            // tangent of input wrt y is [0, 1] -> da/dy = wy
            *(float4*)&dXb[j * PPC + p0] =
                make_float4(c[0] * wy, c[1] * wy, c[2] * wy, c[3] * wy);
        }
    }
    __syncthreads();
    hidden_layer<TANG>(net + W_H,        net + B_H,       X,  dXb, Xn, dXn, jg, pg);
    __syncthreads();
    hidden_layer<TANG>(net + W_H + 4096, net + B_H + 64,  Xn, dXn, X,  dXb, jg, pg);
    __syncthreads();
    hidden_layer<TANG>(net + W_H + 8192, net + B_H + 128, X,  dXb, Xn, dXn, jg, pg);
    __syncthreads();
    if (tid < 32) {
        float acc  = net[B_OUT];
        float dacc = 0.0f;
#pragma unroll 8
        for (int i = 0; i < 64; i++) {
            float w = net[W_OUT + i];
            acc = fmaf(Xn[i * PPC + tid], w, acc);
            if (TANG) dacc = fmaf(dXn[i * PPC + tid], w, dacc);
        }
        outv  = acc;
        doutv = dacc;
    }
}

__global__ __launch_bounds__(NTHR, 1) void fbsnn_main(
    const float* __restrict__ yWin,  const float* __restrict__ yBin,
    const float* __restrict__ yWh,   const float* __restrict__ yBh,
    const float* __restrict__ yWout, const float* __restrict__ yBout,
    const float* __restrict__ qWin,  const float* __restrict__ qBin,
    const float* __restrict__ qWh,   const float* __restrict__ qBh,
    const float* __restrict__ qWout, const float* __restrict__ qBout,
    const float* __restrict__ y0,    const float* __restrict__ dW)
{
    extern __shared__ float sm[];
    const int tid = threadIdx.x;
    const int jg = tid & 15;   // 16 groups of 4 output neurons
    const int pg = tid >> 4;   // 8 groups of 4 paths

    // ---- stage all weights into smem once (reused for all 50 steps) ----
    cpf(sm + W_IN,  yWin, 128,   tid);
    cpf(sm + B_IN,  yBin, 64,    tid);
    cpf(sm + W_H,   yWh,  12288, tid);
    cpf(sm + B_H,   yBh,  192,   tid);
    cpf(sm + W_OUT, yWout, 64,   tid);
    if (tid == 0) sm[B_OUT] = yBout[0];
    float* smq = sm + NET_SZ;
    cpf(smq + W_IN,  qWin, 128,   tid);
    cpf(smq + B_IN,  qBin, 64,    tid);
    cpf(smq + W_H,   qWh,  12288, tid);
    cpf(smq + B_H,   qBh,  192,   tid);
    cpf(smq + W_OUT, qWout, 64,   tid);
    if (tid == 0) smq[B_OUT] = qBout[0];
    if (tid < 32) sm[OFF_YS + tid] = y0[0];
    __syncthreads();

    float Yv = 0.0f, dYv = 0.0f, lossAcc = 0.0f, Ytilde = 0.0f;

    // initial Y_and_grad at t = 0
    eval_net<true>(sm, sm, 0.0f, jg, pg, tid, Yv, dYv);
    __syncthreads();

    const int pbase = blockIdx.x * PPC;

    for (int n = 0; n < NSTEP; n++) {
        float t = (float)n * DTV;

        // q = q_net(t, y)
        float qv = 0.0f, qd_dummy = 0.0f;
        eval_net<false>(smq, sm, t, jg, pg, tid, qv, qd_dummy);
        __syncthreads();

        if (tid < 32) {
            float dwn = SQRT_DT * dW[n * BATCH + pbase + tid];
            float y1  = sm[OFF_YS + tid] + qv * DTV + SIGMA * dwn;
            // Y1_tilde = Y - q^2*dt + (sigma*dY)*dWn
            Ytilde = Yv - qv * qv * DTV + SIGMA * dYv * dwn;
            sm[OFF_YS + tid] = y1;
        }
        __syncthreads();

        // Y1, dY1 at (t+dt, y1)
        eval_net<true>(sm, sm, t + DTV, jg, pg, tid, Yv, dYv);
        __syncthreads();

        if (tid < 32) {
            float e = Yv - Ytilde;
            lossAcc = fmaf(e, e, lossAcc);
        }
    }

    if (tid < 32) {
        float yN = sm[OFF_YS + tid];
        float e1 = Yv - yN * yN;       // terminal value residual
        float e2 = dYv - 2.0f * yN;    // terminal gradient residual
        lossAcc = fmaf(e1, e1, fmaf(e2, e2, lossAcc));
#pragma unroll
        for (int o = 16; o > 0; o >>= 1)
            lossAcc += __shfl_down_sync(0xffffffffu, lossAcc, o);
        if (tid == 0) atomicAdd(&g_acc, lossAcc);
    }
}

extern "C" void kernel_launch(void* const* d_in, const int* in_sizes, int n_in,
                              void* d_out, int out_size)
{
    const float *yWin, *yBin, *yWh, *yBh, *yWout, *yBout;
    const float *qWin, *qBin, *qWh, *qBh, *qWout, *qBout;
    const float *y0, *dW;

    if (in_sizes[0] == 1) {
        // reference-signature order: y0, Y..., q..., dW
        y0    = (const float*)d_in[0];
        yWin  = (const float*)d_in[1];
        yBin  = (const float*)d_in[2];
        yWh   = (const float*)d_in[3];
        yBh   = (const float*)d_in[4];
        yWout = (const float*)d_in[5];
        yBout = (const float*)d_in[6];
        qWin  = (const float*)d_in[7];
        qBin  = (const float*)d_in[8];
        qWh   = (const float*)d_in[9];
        qBh   = (const float*)d_in[10];
        qWout = (const float*)d_in[11];
        qBout = (const float*)d_in[12];
        dW    = (const float*)d_in[13];
    } else {
        // setup_inputs dict order: Y..., q..., y0, dW
        yWin  = (const float*)d_in[0];
        yBin  = (const float*)d_in[1];
        yWh   = (const float*)d_in[2];
        yBh   = (const float*)d_in[3];
        yWout = (const float*)d_in[4];
        yBout = (const float*)d_in[5];
        qWin  = (const float*)d_in[6];
        qBin  = (const float*)d_in[7];
        qWh   = (const float*)d_in[8];
        qBh   = (const float*)d_in[9];
        qWout = (const float*)d_in[10];
        qBout = (const float*)d_in[11];
        y0    = (const float*)d_in[12];
        dW    = (const float*)d_in[13];
    }

    cudaFuncSetAttribute(fbsnn_main, cudaFuncAttributeMaxDynamicSharedMemorySize,
                         SMEM_BYTES);

    k_init<<<1, 1>>>();
    fbsnn_main<<<NCTA, NTHR, SMEM_BYTES>>>(yWin, yBin, yWh, yBh, yWout, yBout,
                                           qWin, qBin, qWh, qBh, qWout, qBout,
                                           y0, dW);
    k_fin<<<1, 1>>>((float*)d_out);
}